// round 13
// baseline (speedup 1.0000x reference)
#include <cuda_runtime.h>
#include <cuda_fp16.h>
#include <cstdint>

// Problem constants
#define B_  32
#define T_  512
#define D_  256
#define F_  256
#define MELMAX_ 2304
#define NTILES 128          // (B_*T_)/128 M-tiles

// smem geometry (bytes)
#define APITCH 144          // 64 fp16 + 8 pad
#define BPITCH 144
#define A_SZ   (128 * APITCH)      // 18432
#define B_SZ   (256 * BPITCH)      // 36864
#define STG    (A_SZ + B_SZ)       // 55296 per stage
#define NSTG   3
#define SMEM_DYN (NSTG * STG)      // 165888
#define SPITCH 264                 // epilogue stage pitch (floats)

// prep kernel block ranges
#define XBLKS  4096                // (B_*T_*D_/4)/256 float4-convert blocks
#define WBLKS  1536                // (2*12*256*64)/256 weight blocks
#define CBLKS  B_                  // cumsum+expand blocks (one per batch)

// ---------------------------------------------------------------------------
// Scratch (no cudaMalloc allowed)
// ---------------------------------------------------------------------------
__device__ __half g_xf[B_ * T_ * D_];
__device__ __half g_h1[B_ * T_ * F_];
// weights: [conv][chunk(12)][f(256)][64] fp16, chunk = tap*4 + dblock
__device__ __half g_wf[2 * 12 * 256 * 64];
__device__ int g_idx[B_ * MELMAX_];

// ---------------------------------------------------------------------------
// PTX helpers
// ---------------------------------------------------------------------------
static __device__ __forceinline__ uint32_t smem_u32(const void* p) {
    uint32_t a;
    asm("{ .reg .u64 t; cvta.to.shared.u64 t, %1; cvt.u32.u64 %0, t; }" : "=r"(a) : "l"(p));
    return a;
}
static __device__ __forceinline__ void cp16(uint32_t saddr, const void* g, int srcsz) {
    asm volatile("cp.async.cg.shared.global [%0], [%1], 16, %2;"
                 :: "r"(saddr), "l"(g), "r"(srcsz) : "memory");
}
static __device__ __forceinline__ void cp_commit() {
    asm volatile("cp.async.commit_group;" ::: "memory");
}
template <int N>
static __device__ __forceinline__ void cp_wait() {
    asm volatile("cp.async.wait_group %0;" :: "n"(N) : "memory");
}
static __device__ __forceinline__ void ldsm_x4(uint32_t addr, uint32_t& r0, uint32_t& r1,
                                               uint32_t& r2, uint32_t& r3) {
    asm volatile("ldmatrix.sync.aligned.m8n8.x4.shared.b16 {%0,%1,%2,%3}, [%4];"
                 : "=r"(r0), "=r"(r1), "=r"(r2), "=r"(r3) : "r"(addr));
}
static __device__ __forceinline__ void mma_f16(float* d, const uint32_t* a, const uint32_t* b) {
    asm volatile(
        "mma.sync.aligned.m16n8k16.row.col.f32.f16.f16.f32 "
        "{%0,%1,%2,%3}, {%4,%5,%6,%7}, {%8,%9}, {%0,%1,%2,%3};"
        : "+f"(d[0]), "+f"(d[1]), "+f"(d[2]), "+f"(d[3])
        : "r"(a[0]), "r"(a[1]), "r"(a[2]), "r"(a[3]), "r"(b[0]), "r"(b[1]));
}

// ---------------------------------------------------------------------------
// Fused prep:
//   blocks [0, XBLKS)              : x fp32 -> fp16
//   blocks [XBLKS, XBLKS+WBLKS)    : weight repack (both convs)
//   blocks [XBLKS+WBLKS, +CBLKS)   : per-batch duration cumsum + idx expansion
// ---------------------------------------------------------------------------
__global__ void prep_kernel(const float4* __restrict__ x4, __half2* __restrict__ xo,
                            const float* __restrict__ w1, const float* __restrict__ w2,
                            __half* __restrict__ wf,
                            const int* __restrict__ target, int* __restrict__ idx) {
    int blk = blockIdx.x;
    int tid = threadIdx.x;
    if (blk < XBLKS) {
        int i = blk * 256 + tid;
        float4 v = x4[i];
        xo[2 * i]     = __floats2half2_rn(v.x, v.y);
        xo[2 * i + 1] = __floats2half2_rn(v.z, v.w);
    } else if (blk < XBLKS + WBLKS) {
        int id = (blk - XBLKS) * 256 + tid;          // < 2*12*256*64
        int cv = id / 196608;
        int r = id - cv * 196608;
        int chunk = r >> 14;
        int rr = r & 16383;                          // f*64 + dc
        int f = rr >> 6, dc = rr & 63;
        int tap = chunk >> 2, db = chunk & 3;
        int d = db * 64 + dc;
        const float* w = cv ? w2 : w1;
        wf[(size_t)cv * 196608 + (size_t)chunk * 16384 + rr] =
            __float2half_rn(w[(f * D_ + d) * 3 + tap]);
    } else {
        // cumsum + expansion for batch b
        __shared__ int sc[T_];
        int b = blk - XBLKS - WBLKS;
        sc[tid]       = target[b * T_ + tid];
        sc[tid + 256] = target[b * T_ + tid + 256];
        __syncthreads();
        for (int off = 1; off < T_; off <<= 1) {
            int v0 = (tid >= off)       ? sc[tid - off]       : 0;
            int v1 = (tid + 256 >= off) ? sc[tid + 256 - off] : 0;
            __syncthreads();
            sc[tid] += v0;
            sc[tid + 256] += v1;
            __syncthreads();
        }
        int* ib = idx + b * MELMAX_;
        #pragma unroll
        for (int h = 0; h < 2; h++) {
            int e = tid + h * 256;
            int hi = sc[e];
            int lo = (e > 0) ? sc[e - 1] : 0;
            for (int p = lo; p < hi && p < MELMAX_; p++) ib[p] = e;
        }
        int total = sc[T_ - 1];
        for (int p = total + tid; p < MELMAX_; p += 256) ib[p] = -1;
    }
}

// ---------------------------------------------------------------------------
// Warp-tile HMMA conv GEMM: Y[128,256] = im2col(X)[128,768] @ W^T, fp16 1-pass
// (one barrier per chunk, 3-stage cp.async, frag double-buffer)
// MODE 0: LN+ReLU -> h (fp16).  MODE 1: LN+ReLU -> dot lin_w -> dur.
// grid: 128 M-tiles, block: 512 (16 warps = 4M x 4N, warp tile 32x64)
// ---------------------------------------------------------------------------
template <int MODE>
__global__ __launch_bounds__(512, 1) void conv_mma_kernel(
    const __half* __restrict__ a_g,
    const __half* __restrict__ wf,    // this conv's base
    const float* __restrict__ bias, const float* __restrict__ gamma,
    const float* __restrict__ beta,
    const float* __restrict__ lw, const float* __restrict__ lb,
    __half* __restrict__ oh,
    float* __restrict__ dur)
{
    extern __shared__ __align__(16) char smem[];
    __shared__ float sbi[256], sg[256], sbt[256], slw[256];
    const uint32_t sb = smem_u32(smem);
    const int tid = threadIdx.x;
    const int lane = tid & 31, wid = tid >> 5;
    const int wm = wid & 3, wn = wid >> 2;     // 4M x 4N warp grid
    const int tile = blockIdx.x;
    const int b = tile >> 2, t0 = (tile & 3) << 7;

    if (tid < 256) {
        sbi[tid] = bias[tid];
        sg[tid]  = gamma[tid];
        sbt[tid] = beta[tid];
        if (MODE == 1) slw[tid] = lw[tid];
    }

    // -------- chunk loader (cp.async, zero-fill at sequence edges) ----------
    auto load_chunk = [&](int c) {
        const int tap = c >> 2, db = c & 3;
        const uint32_t stg = sb + (c % NSTG) * STG;
        // A: 128 rows x 64 fp16  (1024 x 16B)
        #pragma unroll
        for (int i = 0; i < 2; i++) {
            int vid = tid + i * 512;              // 0..1023
            int row = vid >> 3, seg = vid & 7;
            int t = t0 + row + tap - 1;
            int ok = ((unsigned)t < (unsigned)T_) ? 16 : 0;
            int tc = min(max(t, 0), T_ - 1);
            const void* g = a_g + ((size_t)(b * T_ + tc) * D_ + db * 64 + seg * 8);
            cp16(stg + row * APITCH + seg * 16, g, ok);
        }
        // B: 256 rows x 64 fp16  (2048 x 16B)
        {
            const __half* src = wf + (size_t)c * 16384;
            #pragma unroll
            for (int i = 0; i < 4; i++) {
                int vid = tid + i * 512;          // 0..2047
                int f = vid >> 3, seg = vid & 7;
                cp16(stg + A_SZ + f * BPITCH + seg * 16, src + f * 64 + seg * 8, 16);
            }
        }
        cp_commit();
    };

    float d[2][8][4];
    #pragma unroll
    for (int im = 0; im < 2; im++)
        #pragma unroll
        for (int n8 = 0; n8 < 8; n8++)
            #pragma unroll
            for (int q = 0; q < 4; q++) d[im][n8][q] = 0.0f;

    const uint32_t a_row_off = (uint32_t)((wm * 32 + (lane & 15)) * APITCH + (lane >> 4) * 16);
    const uint32_t b_row_off = (uint32_t)((wn * 64 + (lane & 15)) * BPITCH + (lane >> 4) * 16);

    load_chunk(0);
    load_chunk(1);

    for (int c = 0; c < 12; c++) {
        if (c < 11) cp_wait<1>(); else cp_wait<0>();
        __syncthreads();
        // issue next-next chunk load NOW: stage (c+2)%3 == (c-1)%3, fully consumed
        if (c + 2 < 12) load_chunk(c + 2);

        const uint32_t stg = sb + (c % NSTG) * STG;
        const uint32_t a_p = stg + a_row_off;
        const uint32_t b_p = stg + A_SZ + b_row_off;

        uint32_t af[2][2][4], bfr[2][8][2];
        auto lfrag = [&](int k16, int buf) {
            const uint32_t kb = (uint32_t)(k16 * 32);
            #pragma unroll
            for (int im = 0; im < 2; im++)
                ldsm_x4(a_p + im * 16 * APITCH + kb,
                        af[buf][im][0], af[buf][im][1], af[buf][im][2], af[buf][im][3]);
            #pragma unroll
            for (int g = 0; g < 4; g++) {
                uint32_t r0, r1, r2, r3;
                ldsm_x4(b_p + g * 16 * BPITCH + kb, r0, r1, r2, r3);
                bfr[buf][2 * g][0] = r0; bfr[buf][2 * g][1] = r2;
                bfr[buf][2 * g + 1][0] = r1; bfr[buf][2 * g + 1][1] = r3;
            }
        };

        lfrag(0, 0);
        #pragma unroll
        for (int k16 = 0; k16 < 4; k16++) {
            const int cur = k16 & 1;
            if (k16 < 3) lfrag(k16 + 1, cur ^ 1);
            #pragma unroll
            for (int im = 0; im < 2; im++)
                #pragma unroll
                for (int n8 = 0; n8 < 8; n8++)
                    mma_f16(d[im][n8], af[cur][im], bfr[cur][n8]);
        }
    }

    // ---------------- epilogue: stage accum -> LN + ReLU ----------------
    float* stage = (float*)smem;                 // [128][SPITCH]
    __syncthreads();
    {
        const int g = lane >> 2, q = lane & 3;
        #pragma unroll
        for (int im = 0; im < 2; im++)
            #pragma unroll
            for (int n8 = 0; n8 < 8; n8++) {
                int row = wm * 32 + im * 16 + g;
                int col = wn * 64 + n8 * 8 + q * 2;
                stage[row * SPITCH + col]           = d[im][n8][0];
                stage[row * SPITCH + col + 1]       = d[im][n8][1];
                stage[(row + 8) * SPITCH + col]     = d[im][n8][2];
                stage[(row + 8) * SPITCH + col + 1] = d[im][n8][3];
            }
    }
    __syncthreads();

    {
        const int row = tid >> 2, sub = tid & 3;     // 128 rows x 4 threads
        const float* srow = stage + row * SPITCH + sub * 64;
        float s1 = 0.f, s2 = 0.f;
        #pragma unroll
        for (int j = 0; j < 64; j++) {
            float v = srow[j] + sbi[sub * 64 + j];
            s1 += v; s2 += v * v;
        }
        s1 += __shfl_xor_sync(0xFFFFFFFFu, s1, 1);
        s2 += __shfl_xor_sync(0xFFFFFFFFu, s2, 1);
        s1 += __shfl_xor_sync(0xFFFFFFFFu, s1, 2);
        s2 += __shfl_xor_sync(0xFFFFFFFFu, s2, 2);
        float mu  = s1 * (1.0f / 256.0f);
        float var = s2 * (1.0f / 256.0f) - mu * mu;
        float inv = rsqrtf(var + 1e-5f);

        if (MODE == 0) {
            __half2* oh2 = (__half2*)oh;
            const size_t obase = ((size_t)(b * T_ + t0 + row)) * 128 + sub * 32;
            #pragma unroll
            for (int j = 0; j < 32; j++) {
                int c0 = sub * 64 + 2 * j;
                float v0 = srow[2 * j]     + sbi[c0];
                float v1 = srow[2 * j + 1] + sbi[c0 + 1];
                float y0 = fmaxf((v0 - mu) * inv * sg[c0]     + sbt[c0],     0.0f);
                float y1 = fmaxf((v1 - mu) * inv * sg[c0 + 1] + sbt[c0 + 1], 0.0f);
                oh2[obase + j] = __floats2half2_rn(y0, y1);
            }
        } else {
            float sd = 0.f;
            #pragma unroll
            for (int j = 0; j < 64; j++) {
                int cc = sub * 64 + j;
                float v = srow[j] + sbi[cc];
                float y = fmaxf((v - mu) * inv * sg[cc] + sbt[cc], 0.0f);
                sd += y * slw[cc];
            }
            sd += __shfl_xor_sync(0xFFFFFFFFu, sd, 1);
            sd += __shfl_xor_sync(0xFFFFFFFFu, sd, 2);
            if (sub == 0) dur[(size_t)b * T_ + t0 + row] = fmaxf(sd + lb[0], 0.0f);
        }
    }
}

// ---------------------------------------------------------------------------
// Length-regulator gather via precomputed idx — batched phases for MLP:
// 8 idx loads, then 8 x loads, then 8 stores (all independent within a phase).
// grid: (MELMAX/32, B_), block 256 (64 float4-lanes x 4 rows, 8 t per thread)
// ---------------------------------------------------------------------------
__global__ __launch_bounds__(256) void gather_kernel(
    const float4* __restrict__ x4, const int* __restrict__ idx, float4* __restrict__ out4) {
    const int b = blockIdx.y;
    const int f4 = threadIdx.x & 63;
    const int trow = threadIdx.x >> 6;           // 0..3
    const int t0 = blockIdx.x * 32;
    const int tb = b * MELMAX_ + t0 + trow;

    int j[8];
    #pragma unroll
    for (int i = 0; i < 8; i++) j[i] = idx[tb + i * 4];

    const float4 z = make_float4(0.f, 0.f, 0.f, 0.f);
    float4 v[8];
    #pragma unroll
    for (int i = 0; i < 8; i++)
        v[i] = (j[i] >= 0) ? x4[((size_t)b * T_ + j[i]) * 64 + f4] : z;

    const size_t ob = ((size_t)b * MELMAX_ + t0 + trow) * 64 + f4;
    #pragma unroll
    for (int i = 0; i < 8; i++)
        out4[ob + (size_t)i * 4 * 64] = v[i];
}

// ---------------------------------------------------------------------------
extern "C" void kernel_launch(void* const* d_in, const int* in_sizes, int n_in,
                              void* d_out, int out_size) {
    int base = 2;
    if (n_in >= 3 && in_sizes[2] == 1) base = 3;   // scalar mel_max_length present

    const float* x       = (const float*)d_in[0];
    const int*   target  = (const int*)  d_in[1];
    const float* conv1_w = (const float*)d_in[base + 0];
    const float* conv1_b = (const float*)d_in[base + 1];
    const float* ln1_g   = (const float*)d_in[base + 2];
    const float* ln1_b   = (const float*)d_in[base + 3];
    const float* conv2_w = (const float*)d_in[base + 4];
    const float* conv2_b = (const float*)d_in[base + 5];
    const float* ln2_g   = (const float*)d_in[base + 6];
    const float* ln2_b   = (const float*)d_in[base + 7];
    const float* lin_w   = (const float*)d_in[base + 8];
    const float* lin_b   = (const float*)d_in[base + 9];

    float* out_main = (float*)d_out;                                  // [B, MELMAX, D]
    float* out_dur  = (float*)d_out + (size_t)B_ * MELMAX_ * D_;      // [B, T]

    __half *xf, *h1, *wfp;
    int* idx;
    cudaGetSymbolAddress((void**)&xf,  g_xf);
    cudaGetSymbolAddress((void**)&h1,  g_h1);
    cudaGetSymbolAddress((void**)&wfp, g_wf);
    cudaGetSymbolAddress((void**)&idx, g_idx);

    cudaFuncSetAttribute(conv_mma_kernel<0>, cudaFuncAttributeMaxDynamicSharedMemorySize, SMEM_DYN);
    cudaFuncSetAttribute(conv_mma_kernel<1>, cudaFuncAttributeMaxDynamicSharedMemorySize, SMEM_DYN);

    // 1. fused prep: x->fp16 + weight repack + cumsum/idx expansion
    prep_kernel<<<XBLKS + WBLKS + CBLKS, 256>>>((const float4*)x, (__half2*)xf,
                                                conv1_w, conv2_w, wfp, target, idx);

    // 2. conv1 -> h1 fp16
    conv_mma_kernel<0><<<NTILES, 512, SMEM_DYN>>>(xf, wfp, conv1_b, ln1_g, ln1_b,
                                                  nullptr, nullptr, h1, nullptr);
    // 3. conv2 + dur head -> out_dur
    conv_mma_kernel<1><<<NTILES, 512, SMEM_DYN>>>(h1, wfp + (size_t)196608,
                                                  conv2_b, ln2_g, ln2_b,
                                                  lin_w, lin_b, nullptr, out_dur);
    // 4. length-regulator gather (precomputed idx, batched-phase MLP)
    dim3 ggrid(MELMAX_ / 32, B_);
    gather_kernel<<<ggrid, 256>>>((const float4*)x, idx, (float4*)out_main);
}

// round 14
// speedup vs baseline: 1.0306x; 1.0306x over previous
#include <cuda_runtime.h>
#include <cuda_fp16.h>
#include <cstdint>

// Problem constants
#define B_  32
#define T_  512
#define D_  256
#define F_  256
#define MELMAX_ 2304
#define NTILES 128          // (B_*T_)/128 M-tiles

// smem geometry (bytes)
#define APITCH 144          // 64 fp16 + 8 pad
#define BPITCH 144
#define A_SZ   (128 * APITCH)      // 18432
#define B_SZ   (256 * BPITCH)      // 36864
#define STG    (A_SZ + B_SZ)       // 55296 per stage
#define NSTG   3
#define SMEM_DYN (NSTG * STG)      // 165888
#define SPITCH 264                 // epilogue stage pitch (floats)

// prep kernel block ranges
#define XBLKS  4096                // (B_*T_*D_/4)/256 float4-convert blocks
#define WBLKS  1536                // (2*12*256*64)/256 weight blocks
#define CBLKS  B_                  // cumsum+expand blocks (one per batch)

// ---------------------------------------------------------------------------
// Scratch (no cudaMalloc allowed)
// ---------------------------------------------------------------------------
__device__ __half g_xf[B_ * T_ * D_];
__device__ __half g_h1[B_ * T_ * F_];
// weights: [conv][chunk(12)][f(256)][64] fp16, chunk = tap*4 + dblock
__device__ __half g_wf[2 * 12 * 256 * 64];
__device__ int g_idx[B_ * MELMAX_];

// ---------------------------------------------------------------------------
// PTX helpers
// ---------------------------------------------------------------------------
static __device__ __forceinline__ uint32_t smem_u32(const void* p) {
    uint32_t a;
    asm("{ .reg .u64 t; cvta.to.shared.u64 t, %1; cvt.u32.u64 %0, t; }" : "=r"(a) : "l"(p));
    return a;
}
static __device__ __forceinline__ void cp16(uint32_t saddr, const void* g, int srcsz) {
    asm volatile("cp.async.cg.shared.global [%0], [%1], 16, %2;"
                 :: "r"(saddr), "l"(g), "r"(srcsz) : "memory");
}
static __device__ __forceinline__ void cp_commit() {
    asm volatile("cp.async.commit_group;" ::: "memory");
}
template <int N>
static __device__ __forceinline__ void cp_wait() {
    asm volatile("cp.async.wait_group %0;" :: "n"(N) : "memory");
}
static __device__ __forceinline__ void ldsm_x4(uint32_t addr, uint32_t& r0, uint32_t& r1,
                                               uint32_t& r2, uint32_t& r3) {
    asm volatile("ldmatrix.sync.aligned.m8n8.x4.shared.b16 {%0,%1,%2,%3}, [%4];"
                 : "=r"(r0), "=r"(r1), "=r"(r2), "=r"(r3) : "r"(addr));
}
static __device__ __forceinline__ void mma_f16(float* d, const uint32_t* a, const uint32_t* b) {
    asm volatile(
        "mma.sync.aligned.m16n8k16.row.col.f32.f16.f16.f32 "
        "{%0,%1,%2,%3}, {%4,%5,%6,%7}, {%8,%9}, {%0,%1,%2,%3};"
        : "+f"(d[0]), "+f"(d[1]), "+f"(d[2]), "+f"(d[3])
        : "r"(a[0]), "r"(a[1]), "r"(a[2]), "r"(a[3]), "r"(b[0]), "r"(b[1]));
}

// ---------------------------------------------------------------------------
// Fused prep:
//   blocks [0, XBLKS)              : x fp32 -> fp16
//   blocks [XBLKS, XBLKS+WBLKS)    : weight repack (both convs)
//   blocks [XBLKS+WBLKS, +CBLKS)   : per-batch duration cumsum + idx expansion
// ---------------------------------------------------------------------------
__global__ void prep_kernel(const float4* __restrict__ x4, __half2* __restrict__ xo,
                            const float* __restrict__ w1, const float* __restrict__ w2,
                            __half* __restrict__ wf,
                            const int* __restrict__ target, int* __restrict__ idx) {
    int blk = blockIdx.x;
    int tid = threadIdx.x;
    if (blk < XBLKS) {
        int i = blk * 256 + tid;
        float4 v = x4[i];
        xo[2 * i]     = __floats2half2_rn(v.x, v.y);
        xo[2 * i + 1] = __floats2half2_rn(v.z, v.w);
    } else if (blk < XBLKS + WBLKS) {
        int id = (blk - XBLKS) * 256 + tid;          // < 2*12*256*64
        int cv = id / 196608;
        int r = id - cv * 196608;
        int chunk = r >> 14;
        int rr = r & 16383;                          // f*64 + dc
        int f = rr >> 6, dc = rr & 63;
        int tap = chunk >> 2, db = chunk & 3;
        int d = db * 64 + dc;
        const float* w = cv ? w2 : w1;
        wf[(size_t)cv * 196608 + (size_t)chunk * 16384 + rr] =
            __float2half_rn(w[(f * D_ + d) * 3 + tap]);
    } else {
        // cumsum + expansion for batch b
        __shared__ int sc[T_];
        int b = blk - XBLKS - WBLKS;
        sc[tid]       = target[b * T_ + tid];
        sc[tid + 256] = target[b * T_ + tid + 256];
        __syncthreads();
        for (int off = 1; off < T_; off <<= 1) {
            int v0 = (tid >= off)       ? sc[tid - off]       : 0;
            int v1 = (tid + 256 >= off) ? sc[tid + 256 - off] : 0;
            __syncthreads();
            sc[tid] += v0;
            sc[tid + 256] += v1;
            __syncthreads();
        }
        int* ib = idx + b * MELMAX_;
        #pragma unroll
        for (int h = 0; h < 2; h++) {
            int e = tid + h * 256;
            int hi = sc[e];
            int lo = (e > 0) ? sc[e - 1] : 0;
            for (int p = lo; p < hi && p < MELMAX_; p++) ib[p] = e;
        }
        int total = sc[T_ - 1];
        for (int p = total + tid; p < MELMAX_; p += 256) ib[p] = -1;
    }
}

// ---------------------------------------------------------------------------
// Warp-tile HMMA conv GEMM: Y[128,256] = im2col(X)[128,768] @ W^T, fp16 1-pass
// (one barrier per chunk, 3-stage cp.async, frag double-buffer)
// MODE 0: LN+ReLU -> h (fp16).  MODE 1: LN+ReLU -> dot lin_w -> dur.
// grid: 128 M-tiles, block: 512 (16 warps = 4M x 4N, warp tile 32x64)
// ---------------------------------------------------------------------------
template <int MODE>
__global__ __launch_bounds__(512, 1) void conv_mma_kernel(
    const __half* __restrict__ a_g,
    const __half* __restrict__ wf,    // this conv's base
    const float* __restrict__ bias, const float* __restrict__ gamma,
    const float* __restrict__ beta,
    const float* __restrict__ lw, const float* __restrict__ lb,
    __half* __restrict__ oh,
    float* __restrict__ dur)
{
    extern __shared__ __align__(16) char smem[];
    __shared__ float sbi[256], sg[256], sbt[256], slw[256];
    const uint32_t sb = smem_u32(smem);
    const int tid = threadIdx.x;
    const int lane = tid & 31, wid = tid >> 5;
    const int wm = wid & 3, wn = wid >> 2;     // 4M x 4N warp grid
    const int tile = blockIdx.x;
    const int b = tile >> 2, t0 = (tile & 3) << 7;

    if (tid < 256) {
        sbi[tid] = bias[tid];
        sg[tid]  = gamma[tid];
        sbt[tid] = beta[tid];
        if (MODE == 1) slw[tid] = lw[tid];
    }

    // -------- chunk loader (cp.async, zero-fill at sequence edges) ----------
    auto load_chunk = [&](int c) {
        const int tap = c >> 2, db = c & 3;
        const uint32_t stg = sb + (c % NSTG) * STG;
        // A: 128 rows x 64 fp16  (1024 x 16B)
        #pragma unroll
        for (int i = 0; i < 2; i++) {
            int vid = tid + i * 512;              // 0..1023
            int row = vid >> 3, seg = vid & 7;
            int t = t0 + row + tap - 1;
            int ok = ((unsigned)t < (unsigned)T_) ? 16 : 0;
            int tc = min(max(t, 0), T_ - 1);
            const void* g = a_g + ((size_t)(b * T_ + tc) * D_ + db * 64 + seg * 8);
            cp16(stg + row * APITCH + seg * 16, g, ok);
        }
        // B: 256 rows x 64 fp16  (2048 x 16B)
        {
            const __half* src = wf + (size_t)c * 16384;
            #pragma unroll
            for (int i = 0; i < 4; i++) {
                int vid = tid + i * 512;          // 0..2047
                int f = vid >> 3, seg = vid & 7;
                cp16(stg + A_SZ + f * BPITCH + seg * 16, src + f * 64 + seg * 8, 16);
            }
        }
        cp_commit();
    };

    float d[2][8][4];
    #pragma unroll
    for (int im = 0; im < 2; im++)
        #pragma unroll
        for (int n8 = 0; n8 < 8; n8++)
            #pragma unroll
            for (int q = 0; q < 4; q++) d[im][n8][q] = 0.0f;

    const uint32_t a_row_off = (uint32_t)((wm * 32 + (lane & 15)) * APITCH + (lane >> 4) * 16);
    const uint32_t b_row_off = (uint32_t)((wn * 64 + (lane & 15)) * BPITCH + (lane >> 4) * 16);

    load_chunk(0);
    load_chunk(1);

    for (int c = 0; c < 12; c++) {
        if (c < 11) cp_wait<1>(); else cp_wait<0>();
        __syncthreads();
        // issue next-next chunk load NOW: stage (c+2)%3 == (c-1)%3, fully consumed
        if (c + 2 < 12) load_chunk(c + 2);

        const uint32_t stg = sb + (c % NSTG) * STG;
        const uint32_t a_p = stg + a_row_off;
        const uint32_t b_p = stg + A_SZ + b_row_off;

        uint32_t af[2][2][4], bfr[2][8][2];
        auto lfrag = [&](int k16, int buf) {
            const uint32_t kb = (uint32_t)(k16 * 32);
            #pragma unroll
            for (int im = 0; im < 2; im++)
                ldsm_x4(a_p + im * 16 * APITCH + kb,
                        af[buf][im][0], af[buf][im][1], af[buf][im][2], af[buf][im][3]);
            #pragma unroll
            for (int g = 0; g < 4; g++) {
                uint32_t r0, r1, r2, r3;
                ldsm_x4(b_p + g * 16 * BPITCH + kb, r0, r1, r2, r3);
                bfr[buf][2 * g][0] = r0; bfr[buf][2 * g][1] = r2;
                bfr[buf][2 * g + 1][0] = r1; bfr[buf][2 * g + 1][1] = r3;
            }
        };

        lfrag(0, 0);
        #pragma unroll
        for (int k16 = 0; k16 < 4; k16++) {
            const int cur = k16 & 1;
            if (k16 < 3) lfrag(k16 + 1, cur ^ 1);
            #pragma unroll
            for (int im = 0; im < 2; im++)
                #pragma unroll
                for (int n8 = 0; n8 < 8; n8++)
                    mma_f16(d[im][n8], af[cur][im], bfr[cur][n8]);
        }
    }

    // ---------------- epilogue: stage accum -> LN + ReLU ----------------
    float* stage = (float*)smem;                 // [128][SPITCH]
    __syncthreads();
    {
        const int g = lane >> 2, q = lane & 3;
        #pragma unroll
        for (int im = 0; im < 2; im++)
            #pragma unroll
            for (int n8 = 0; n8 < 8; n8++) {
                int row = wm * 32 + im * 16 + g;
                int col = wn * 64 + n8 * 8 + q * 2;
                stage[row * SPITCH + col]           = d[im][n8][0];
                stage[row * SPITCH + col + 1]       = d[im][n8][1];
                stage[(row + 8) * SPITCH + col]     = d[im][n8][2];
                stage[(row + 8) * SPITCH + col + 1] = d[im][n8][3];
            }
    }
    __syncthreads();

    {
        const int row = tid >> 2, sub = tid & 3;     // 128 rows x 4 threads
        const float* srow = stage + row * SPITCH + sub * 64;
        float s1 = 0.f, s2 = 0.f;
        #pragma unroll
        for (int j = 0; j < 64; j++) {
            float v = srow[j] + sbi[sub * 64 + j];
            s1 += v; s2 += v * v;
        }
        s1 += __shfl_xor_sync(0xFFFFFFFFu, s1, 1);
        s2 += __shfl_xor_sync(0xFFFFFFFFu, s2, 1);
        s1 += __shfl_xor_sync(0xFFFFFFFFu, s1, 2);
        s2 += __shfl_xor_sync(0xFFFFFFFFu, s2, 2);
        float mu  = s1 * (1.0f / 256.0f);
        float var = s2 * (1.0f / 256.0f) - mu * mu;
        float inv = rsqrtf(var + 1e-5f);

        if (MODE == 0) {
            __half2* oh2 = (__half2*)oh;
            const size_t obase = ((size_t)(b * T_ + t0 + row)) * 128 + sub * 32;
            #pragma unroll
            for (int j = 0; j < 32; j++) {
                int c0 = sub * 64 + 2 * j;
                float v0 = srow[2 * j]     + sbi[c0];
                float v1 = srow[2 * j + 1] + sbi[c0 + 1];
                float y0 = fmaxf((v0 - mu) * inv * sg[c0]     + sbt[c0],     0.0f);
                float y1 = fmaxf((v1 - mu) * inv * sg[c0 + 1] + sbt[c0 + 1], 0.0f);
                oh2[obase + j] = __floats2half2_rn(y0, y1);
            }
        } else {
            float sd = 0.f;
            #pragma unroll
            for (int j = 0; j < 64; j++) {
                int cc = sub * 64 + j;
                float v = srow[j] + sbi[cc];
                float y = fmaxf((v - mu) * inv * sg[cc] + sbt[cc], 0.0f);
                sd += y * slw[cc];
            }
            sd += __shfl_xor_sync(0xFFFFFFFFu, sd, 1);
            sd += __shfl_xor_sync(0xFFFFFFFFu, sd, 2);
            if (sub == 0) dur[(size_t)b * T_ + t0 + row] = fmaxf(sd + lb[0], 0.0f);
        }
    }
}

// ---------------------------------------------------------------------------
// Length-regulator gather via precomputed idx (float4 streaming)
// ---------------------------------------------------------------------------
__global__ __launch_bounds__(256) void gather_kernel(
    const float4* __restrict__ x4, const int* __restrict__ idx, float4* __restrict__ out4) {
    const int b = blockIdx.y;
    const int f4 = threadIdx.x & 63;
    const int trow = threadIdx.x >> 6;           // 0..3
    const int t0 = blockIdx.x * 32;
    const int tb = b * MELMAX_ + t0 + trow;

    int j[8];
    #pragma unroll
    for (int i = 0; i < 8; i++) j[i] = idx[tb + i * 4];

    const float4 z = make_float4(0.f, 0.f, 0.f, 0.f);
    float4 v[8];
    #pragma unroll
    for (int i = 0; i < 8; i++)
        v[i] = (j[i] >= 0) ? x4[((size_t)b * T_ + j[i]) * 64 + f4] : z;

    const size_t ob = ((size_t)b * MELMAX_ + t0 + trow) * 64 + f4;
    #pragma unroll
    for (int i = 0; i < 8; i++)
        out4[ob + (size_t)i * 4 * 64] = v[i];
}

// ---------------------------------------------------------------------------
extern "C" void kernel_launch(void* const* d_in, const int* in_sizes, int n_in,
                              void* d_out, int out_size) {
    int base = 2;
    if (n_in >= 3 && in_sizes[2] == 1) base = 3;   // scalar mel_max_length present

    const float* x       = (const float*)d_in[0];
    const int*   target  = (const int*)  d_in[1];
    const float* conv1_w = (const float*)d_in[base + 0];
    const float* conv1_b = (const float*)d_in[base + 1];
    const float* ln1_g   = (const float*)d_in[base + 2];
    const float* ln1_b   = (const float*)d_in[base + 3];
    const float* conv2_w = (const float*)d_in[base + 4];
    const float* conv2_b = (const float*)d_in[base + 5];
    const float* ln2_g   = (const float*)d_in[base + 6];
    const float* ln2_b   = (const float*)d_in[base + 7];
    const float* lin_w   = (const float*)d_in[base + 8];
    const float* lin_b   = (const float*)d_in[base + 9];

    float* out_main = (float*)d_out;                                  // [B, MELMAX, D]
    float* out_dur  = (float*)d_out + (size_t)B_ * MELMAX_ * D_;      // [B, T]

    __half *xf, *h1, *wfp;
    int* idx;
    cudaGetSymbolAddress((void**)&xf,  g_xf);
    cudaGetSymbolAddress((void**)&h1,  g_h1);
    cudaGetSymbolAddress((void**)&wfp, g_wf);
    cudaGetSymbolAddress((void**)&idx, g_idx);

    cudaFuncSetAttribute(conv_mma_kernel<0>, cudaFuncAttributeMaxDynamicSharedMemorySize, SMEM_DYN);
    cudaFuncSetAttribute(conv_mma_kernel<1>, cudaFuncAttributeMaxDynamicSharedMemorySize, SMEM_DYN);

    // side stream + fork/join events (created once; host-side objects only)
    static cudaStream_t s2 = nullptr;
    static cudaEvent_t ev_fork = nullptr, ev_join = nullptr;
    if (s2 == nullptr) {
        cudaStreamCreateWithFlags(&s2, cudaStreamNonBlocking);
        cudaEventCreateWithFlags(&ev_fork, cudaEventDisableTiming);
        cudaEventCreateWithFlags(&ev_join, cudaEventDisableTiming);
    }

    // 1. fused prep: x->fp16 + weight repack + cumsum/idx expansion (main stream)
    prep_kernel<<<XBLKS + WBLKS + CBLKS, 256>>>((const float4*)x, (__half2*)xf,
                                                conv1_w, conv2_w, wfp, target, idx);

    // fork: gather runs on side stream, overlapping both convs
    cudaEventRecord(ev_fork, 0);
    cudaStreamWaitEvent(s2, ev_fork, 0);
    dim3 ggrid(MELMAX_ / 32, B_);
    gather_kernel<<<ggrid, 256, 0, s2>>>((const float4*)x, idx, (float4*)out_main);
    cudaEventRecord(ev_join, s2);

    // 2. conv1 -> h1 fp16 (main stream, concurrent with gather)
    conv_mma_kernel<0><<<NTILES, 512, SMEM_DYN>>>(xf, wfp, conv1_b, ln1_g, ln1_b,
                                                  nullptr, nullptr, h1, nullptr);
    // 3. conv2 + dur head -> out_dur
    conv_mma_kernel<1><<<NTILES, 512, SMEM_DYN>>>(h1, wfp + (size_t)196608,
                                                  conv2_b, ln2_g, ln2_b,
                                                  lin_w, lin_b, nullptr, out_dur);

    // join: main stream completion implies gather done
    cudaStreamWaitEvent(0, ev_join, 0);
}